// round 4
// baseline (speedup 1.0000x reference)
#include <cuda_runtime.h>
#include <cuda_bf16.h>
#include <math.h>

// Problem constants
#define BB    4096
#define TT    32
#define VOCAB 10000
#define EE    300
#define HH    300
#define KP    304      // K padded to multiple of 8 (38 * 8)
#define NP    1280     // 4H=1200 padded to multiple of 128
#define MV    10112    // VOCAB padded to multiple of 128 (79 * 128)

// ---------------- device scratch (static, no allocations) ----------------
__device__ float g_emb_pad[MV * KP];         // padded embedding table   (~12.3 MB)
__device__ float g_wih[NP * KP];             // W_ih, gate-interleaved + padded
__device__ float g_whh[NP * KP];             // W_hh, gate-interleaved + padded
__device__ float g_bias[NP];                 // b_ih + b_hh, gate-interleaved
__device__ float g_xproj[MV * NP];           // embed @ W_ih^T            (~51.8 MB)
__device__ float g_h[2][BB * KP];            // hidden state double buffer
__device__ float g_c[BB * KP];               // cell state
__device__ float g_hlast[BB * HH];           // last valid hidden per sample
__device__ float g_wn[2 * HH];               // weight-normed classifier

// ---------------- prep: pad/permute weights, zero state ----------------
// Gate interleave: padded column n' = 4*u + gate  <->  source row gate*H + u
__global__ void k_prep(const float* __restrict__ embed_w,
                       const float* __restrict__ W_ih,
                       const float* __restrict__ W_hh,
                       const float* __restrict__ b_ih,
                       const float* __restrict__ b_hh)
{
    const int stride = gridDim.x * blockDim.x;
    const int i0 = blockIdx.x * blockDim.x + threadIdx.x;

    for (int idx = i0; idx < MV * KP; idx += stride) {
        int r = idx / KP, k = idx - r * KP;
        g_emb_pad[idx] = (r < VOCAB && k < EE) ? embed_w[r * EE + k] : 0.f;
    }
    for (int idx = i0; idx < NP * KP; idx += stride) {
        int n = idx / KP, k = idx - n * KP;
        int gs = n & 3, u = n >> 2;
        float vi = 0.f, vh = 0.f;
        if (u < HH && k < EE) {
            int s = (gs * HH + u) * EE + k;
            vi = W_ih[s];
            vh = W_hh[s];
        }
        g_wih[idx] = vi;
        g_whh[idx] = vh;
    }
    for (int n = i0; n < NP; n += stride) {
        int gs = n & 3, u = n >> 2;
        g_bias[n] = (u < HH) ? (b_ih[gs * HH + u] + b_hh[gs * HH + u]) : 0.f;
    }
    for (int idx = i0; idx < BB * KP; idx += stride) {
        g_h[0][idx] = 0.f;
        g_h[1][idx] = 0.f;
        g_c[idx]    = 0.f;
    }
}

// weight-normed classifier: W = g * v / ||v||_row   (2 rows of 300)
__global__ void k_prep_cls(const float* __restrict__ cls_v,
                           const float* __restrict__ cls_g)
{
    int w = threadIdx.x >> 5;      // warp -> class row
    int lane = threadIdx.x & 31;
    if (w >= 2) return;
    float s = 0.f;
    for (int k = lane; k < HH; k += 32) {
        float v = cls_v[w * HH + k];
        s += v * v;
    }
    #pragma unroll
    for (int o = 16; o; o >>= 1) s += __shfl_xor_sync(0xffffffff, s, o);
    float scale = cls_g[w] / sqrtf(s);
    for (int k = lane; k < HH; k += 32)
        g_wn[w * HH + k] = cls_v[w * HH + k] * scale;
}

// ---------------- GEMM C = A[M,KP] * B[N,KP]^T  (both row-major, K-contig) ----------------
// MODE 0: A=g_emb_pad, B=g_wih, store C into g_xproj (x_proj precompute)
// MODE 1: A=g_h[parity], B=g_whh, fused LSTM epilogue (reads g_xproj gather,
//         bias, c; writes c, h[parity^1], h_last)
template <int MODE>
__global__ void __launch_bounds__(256) k_gemm(int t, int parity,
                                              const int* __restrict__ cap,
                                              const int* __restrict__ cap_len)
{
    __shared__ float As[8][128];
    __shared__ float Bs[8][128];
    __shared__ int   s_cap[128];
    __shared__ int   s_len[128];

    const float* A  = (MODE == 0) ? g_emb_pad : g_h[parity];
    const float* Bw = (MODE == 0) ? g_wih : g_whh;

    const int tid = threadIdx.x;
    const int tx = tid & 15;   // n direction (16)
    const int ty = tid >> 4;   // m direction (16)
    const int m0 = blockIdx.y * 128;
    const int n0 = blockIdx.x * 128;

    if (MODE == 1 && tid < 128) {
        int r = m0 + tid;
        s_cap[tid] = cap[r * TT + t];
        s_len[tid] = cap_len[r];
    }

    const float* Ap = A  + (size_t)m0 * KP;
    const float* Bp = Bw + (size_t)n0 * KP;
    const int lr = tid >> 1;         // 0..127 (row within tile)
    const int lc = (tid & 1) * 4;    // 0 or 4 (k offset of float4)

    float acc[8][8];
    #pragma unroll
    for (int i = 0; i < 8; i++)
        #pragma unroll
        for (int j = 0; j < 8; j++) acc[i][j] = 0.f;

    float4 av = *(const float4*)(Ap + lr * KP + lc);
    float4 bv = *(const float4*)(Bp + lr * KP + lc);

    for (int k0 = 0; k0 < KP; k0 += 8) {
        __syncthreads();
        As[lc + 0][lr] = av.x; As[lc + 1][lr] = av.y;
        As[lc + 2][lr] = av.z; As[lc + 3][lr] = av.w;
        Bs[lc + 0][lr] = bv.x; Bs[lc + 1][lr] = bv.y;
        Bs[lc + 2][lr] = bv.z; Bs[lc + 3][lr] = bv.w;
        __syncthreads();
        if (k0 + 8 < KP) {   // prefetch next tile into registers
            av = *(const float4*)(Ap + lr * KP + k0 + 8 + lc);
            bv = *(const float4*)(Bp + lr * KP + k0 + 8 + lc);
        }
        #pragma unroll
        for (int k = 0; k < 8; k++) {
            float4 a0 = *(const float4*)&As[k][ty * 8];
            float4 a1 = *(const float4*)&As[k][ty * 8 + 4];
            float4 b0 = *(const float4*)&Bs[k][tx * 8];
            float4 b1 = *(const float4*)&Bs[k][tx * 8 + 4];
            float ar[8] = {a0.x, a0.y, a0.z, a0.w, a1.x, a1.y, a1.z, a1.w};
            float br[8] = {b0.x, b0.y, b0.z, b0.w, b1.x, b1.y, b1.z, b1.w};
            #pragma unroll
            for (int i = 0; i < 8; i++)
                #pragma unroll
                for (int j = 0; j < 8; j++)
                    acc[i][j] += ar[i] * br[j];
        }
    }

    if (MODE == 0) {
        #pragma unroll
        for (int i = 0; i < 8; i++) {
            float* dst = g_xproj + (size_t)(m0 + ty * 8 + i) * NP + n0 + tx * 8;
            float4 v0 = {acc[i][0], acc[i][1], acc[i][2], acc[i][3]};
            float4 v1 = {acc[i][4], acc[i][5], acc[i][6], acc[i][7]};
            *(float4*)dst = v0;
            *(float4*)(dst + 4) = v1;
        }
    } else {
        const int nb  = n0 + tx * 8;   // 8 interleaved gate cols = 2 hidden units
        const int hu0 = nb >> 2;
        float* hout = g_h[parity ^ 1];
        const float4 bi0 = *(const float4*)(g_bias + nb);
        const float4 bi1 = *(const float4*)(g_bias + nb + 4);
        #pragma unroll
        for (int i = 0; i < 8; i++) {
            const int lrow = ty * 8 + i;
            const int r = m0 + lrow;
            const float* xg = g_xproj + (size_t)s_cap[lrow] * NP + nb;
            const float4 x0 = *(const float4*)xg;
            const float4 x1 = *(const float4*)(xg + 4);
            const bool lastt = (t == s_len[lrow] - 1);
            // hidden unit 0 of this thread's tile
            if (hu0 < HH) {
                float gi = acc[i][0] + x0.x + bi0.x;
                float gf = acc[i][1] + x0.y + bi0.y;
                float gg = acc[i][2] + x0.z + bi0.z;
                float go = acc[i][3] + x0.w + bi0.w;
                float I = 1.f / (1.f + expf(-gi));
                float F = 1.f / (1.f + expf(-gf));
                float G = tanhf(gg);
                float O = 1.f / (1.f + expf(-go));
                float cn = F * g_c[r * KP + hu0] + I * G;
                float hn = O * tanhf(cn);
                g_c[r * KP + hu0] = cn;
                hout[r * KP + hu0] = hn;
                if (lastt) g_hlast[r * HH + hu0] = hn;
            }
            // hidden unit 1
            int hu1 = hu0 + 1;
            if (hu1 < HH) {
                float gi = acc[i][4] + x1.x + bi1.x;
                float gf = acc[i][5] + x1.y + bi1.y;
                float gg = acc[i][6] + x1.z + bi1.z;
                float go = acc[i][7] + x1.w + bi1.w;
                float I = 1.f / (1.f + expf(-gi));
                float F = 1.f / (1.f + expf(-gf));
                float G = tanhf(gg);
                float O = 1.f / (1.f + expf(-go));
                float cn = F * g_c[r * KP + hu1] + I * G;
                float hn = O * tanhf(cn);
                g_c[r * KP + hu1] = cn;
                hout[r * KP + hu1] = hn;
                if (lastt) g_hlast[r * HH + hu1] = hn;
            }
        }
    }
}

// ---------------- classifier: out[b, n] = h_last[b,:] . Wn[n,:] + cls_b[n] ----------------
__global__ void k_cls(const float* __restrict__ cls_b, float* __restrict__ out)
{
    int warp = (blockIdx.x * blockDim.x + threadIdx.x) >> 5;
    int lane = threadIdx.x & 31;
    if (warp >= BB) return;
    float s0 = 0.f, s1 = 0.f;
    for (int k = lane; k < HH; k += 32) {
        float hv = g_hlast[warp * HH + k];
        s0 += hv * g_wn[k];
        s1 += hv * g_wn[HH + k];
    }
    #pragma unroll
    for (int o = 16; o; o >>= 1) {
        s0 += __shfl_xor_sync(0xffffffff, s0, o);
        s1 += __shfl_xor_sync(0xffffffff, s1, o);
    }
    if (lane == 0) {
        out[warp * 2 + 0] = s0 + cls_b[0];
        out[warp * 2 + 1] = s1 + cls_b[1];
    }
}

extern "C" void kernel_launch(void* const* d_in, const int* in_sizes, int n_in,
                              void* d_out, int out_size)
{
    const int*   cap     = (const int*)d_in[0];
    const int*   cap_len = (const int*)d_in[1];
    const float* embed_w = (const float*)d_in[2];
    const float* W_ih    = (const float*)d_in[3];
    const float* W_hh    = (const float*)d_in[4];
    const float* b_ih    = (const float*)d_in[5];
    const float* b_hh    = (const float*)d_in[6];
    const float* cls_v   = (const float*)d_in[7];
    const float* cls_g   = (const float*)d_in[8];
    const float* cls_b   = (const float*)d_in[9];
    float* out = (float*)d_out;

    // 1) pad/permute weights, zero h/c, weight-norm classifier
    k_prep<<<1024, 256>>>(embed_w, W_ih, W_hh, b_ih, b_hh);
    k_prep_cls<<<1, 64>>>(cls_v, cls_g);

    // 2) x_proj = embed @ W_ih^T   (vocab-sized, one big GEMM)
    {
        dim3 grid(NP / 128, MV / 128);   // (10, 79)
        k_gemm<0><<<grid, 256>>>(0, 0, nullptr, nullptr);
    }

    // 3) 32 fused recurrent steps: gates = h @ W_hh^T (+gathered x_proj +bias) -> LSTM update
    {
        dim3 grid(NP / 128, BB / 128);   // (10, 32)
        for (int t = 0; t < TT; t++)
            k_gemm<1><<<grid, 256>>>(t, t & 1, cap, cap_len);
    }

    // 4) classifier
    k_cls<<<512, 256>>>(cls_b, out);
}

// round 6
// speedup vs baseline: 1.4857x; 1.4857x over previous
#include <cuda_runtime.h>
#include <cuda_bf16.h>
#include <math.h>
#include <stdint.h>

// ---------------- problem constants ----------------
#define BB    4096
#define TT    32
#define VOCAB 10000
#define EE    300
#define HH    300
#define KSEG  320      // padded K per segment
#define KP2   640      // hi|lo storage columns
#define NP    1280     // 4H padded
#define MV    10112    // vocab padded to 128
#define NC    30       // K chunks of 32 (3 segments x 10)
#define MT    128
#define NT    256

// smem (dynamic) layout, bytes
#define SM_CAP   0          // 128 int
#define SM_LEN   512        // 128 int
#define SM_BIAS  1024       // 256 float
#define SM_STAGE 2048       // 3 stages x (A 10240 + B 20480)
#define STAGE_BYTES 30720
#define SMEM_TOTAL (SM_STAGE + 3 * STAGE_BYTES)   // 94208

// ---------------- device scratch ----------------
__device__ __nv_bfloat16 g_emb2[(size_t)MV * KP2];
__device__ __nv_bfloat16 g_wih2[(size_t)NP * KP2];
__device__ __nv_bfloat16 g_whh2[(size_t)NP * KP2];
__device__ float         g_bias[NP];
__device__ float         g_xproj[(size_t)MV * NP];
__device__ __nv_bfloat16 g_h2[2][(size_t)BB * KP2];
__device__ float         g_c[(size_t)BB * KSEG];
__device__ float         g_hlast[BB * HH];
__device__ float         g_wn[2 * HH];

// ---------------- PTX helpers (plain sm_80+ instructions only) ----------------
__device__ __forceinline__ uint32_t smem_u32(const void* p) {
    uint32_t a;
    asm("{ .reg .u64 t; cvta.to.shared.u64 t, %1; cvt.u32.u64 %0, t; }" : "=r"(a) : "l"(p));
    return a;
}
__device__ __forceinline__ void cp_async16(uint32_t s, const void* g) {
    asm volatile("cp.async.cg.shared.global [%0], [%1], 16;" :: "r"(s), "l"(g) : "memory");
}
__device__ __forceinline__ void cp_commit() {
    asm volatile("cp.async.commit_group;" ::: "memory");
}
__device__ __forceinline__ void cp_wait1() {
    asm volatile("cp.async.wait_group 1;" ::: "memory");
}
__device__ __forceinline__ void ldsm_x4(uint32_t* r, uint32_t addr) {
    asm volatile("ldmatrix.sync.aligned.m8n8.x4.shared.b16 {%0,%1,%2,%3}, [%4];"
                 : "=r"(r[0]), "=r"(r[1]), "=r"(r[2]), "=r"(r[3]) : "r"(addr));
}
__device__ __forceinline__ void ldsm_x2(uint32_t* r, uint32_t addr) {
    asm volatile("ldmatrix.sync.aligned.m8n8.x2.shared.b16 {%0,%1}, [%2];"
                 : "=r"(r[0]), "=r"(r[1]) : "r"(addr));
}
__device__ __forceinline__ void mma16816(float* c, const uint32_t* a, const uint32_t* b) {
    asm volatile(
        "mma.sync.aligned.m16n8k16.row.col.f32.bf16.bf16.f32 "
        "{%0,%1,%2,%3}, {%4,%5,%6,%7}, {%8,%9}, {%0,%1,%2,%3};"
        : "+f"(c[0]), "+f"(c[1]), "+f"(c[2]), "+f"(c[3])
        : "r"(a[0]), "r"(a[1]), "r"(a[2]), "r"(a[3]), "r"(b[0]), "r"(b[1]));
}
__device__ __forceinline__ float fsig(float x)  { return 1.f / (1.f + __expf(-x)); }
__device__ __forceinline__ float ftanh(float x) { return 1.f - 2.f / (1.f + __expf(2.f * x)); }

// ---------------- prep: fp32 -> bf16 hi|lo split, gate interleave, zero state ----------------
__global__ void k_prep(const float* __restrict__ embed_w,
                       const float* __restrict__ W_ih,
                       const float* __restrict__ W_hh,
                       const float* __restrict__ b_ih,
                       const float* __restrict__ b_hh)
{
    const int stride = gridDim.x * blockDim.x;
    const int i0 = blockIdx.x * blockDim.x + threadIdx.x;

    for (size_t idx = i0; idx < (size_t)MV * KP2; idx += stride) {
        int r = idx / KP2, k2 = idx - (size_t)r * KP2;
        int k = (k2 >= KSEG) ? k2 - KSEG : k2;
        float v = (r < VOCAB && k < EE) ? embed_w[r * EE + k] : 0.f;
        __nv_bfloat16 hi = __float2bfloat16_rn(v);
        g_emb2[idx] = (k2 >= KSEG) ? __float2bfloat16_rn(v - __bfloat162float(hi)) : hi;
    }
    for (size_t idx = i0; idx < (size_t)NP * KP2; idx += stride) {
        int n = idx / KP2, k2 = idx - (size_t)n * KP2;
        int k = (k2 >= KSEG) ? k2 - KSEG : k2;
        int gs = n & 3, u = n >> 2;
        float vi = 0.f, vh = 0.f;
        if (u < HH && k < EE) {
            int s = (gs * HH + u) * EE + k;
            vi = W_ih[s];
            vh = W_hh[s];
        }
        __nv_bfloat16 hi_i = __float2bfloat16_rn(vi);
        __nv_bfloat16 hi_h = __float2bfloat16_rn(vh);
        if (k2 >= KSEG) {
            g_wih2[idx] = __float2bfloat16_rn(vi - __bfloat162float(hi_i));
            g_whh2[idx] = __float2bfloat16_rn(vh - __bfloat162float(hi_h));
        } else {
            g_wih2[idx] = hi_i;
            g_whh2[idx] = hi_h;
        }
    }
    for (int n = i0; n < NP; n += stride) {
        int gs = n & 3, u = n >> 2;
        g_bias[n] = (u < HH) ? (b_ih[gs * HH + u] + b_hh[gs * HH + u]) : 0.f;
    }
    for (size_t idx = i0; idx < (size_t)BB * KP2; idx += stride) {
        g_h2[0][idx] = __float2bfloat16_rn(0.f);
        g_h2[1][idx] = __float2bfloat16_rn(0.f);
    }
    for (size_t idx = i0; idx < (size_t)BB * KSEG; idx += stride)
        g_c[idx] = 0.f;
}

__global__ void k_prep_cls(const float* __restrict__ cls_v,
                           const float* __restrict__ cls_g)
{
    int w = threadIdx.x >> 5;
    int lane = threadIdx.x & 31;
    if (w >= 2) return;
    float s = 0.f;
    for (int k = lane; k < HH; k += 32) {
        float v = cls_v[w * HH + k];
        s += v * v;
    }
    #pragma unroll
    for (int o = 16; o; o >>= 1) s += __shfl_xor_sync(0xffffffff, s, o);
    float scale = cls_g[w] / sqrtf(s);
    for (int k = lane; k < HH; k += 32)
        g_wn[w * HH + k] = cls_v[w * HH + k] * scale;
}

// ---------------- HMMA GEMM: C[128,256] = A[128,960] x B[256,960]^T ----------------
// Extended K: A chunks [hi|lo|hi], B chunks [hi|hi|lo]  (exact-ish fp32 via 3x bf16)
// MODE 0: A=g_emb2, B=g_wih2 -> store g_xproj
// MODE 1: A=g_h2[parity], B=g_whh2 -> fused LSTM epilogue
template <int MODE>
__global__ void __launch_bounds__(512, 1) k_tgemm(int t, int parity,
                                                  const int* __restrict__ cap,
                                                  const int* __restrict__ cap_len)
{
    extern __shared__ char smem[];
    const uint32_t sb = smem_u32(smem);
    const int tid = threadIdx.x;
    const int wid = tid >> 5;
    const int lane = tid & 31;
    const int wm = wid >> 3;         // 0..1 : 64-row slice
    const int wn = wid & 7;          // 0..7 : 32-col slice
    const int m0 = blockIdx.y * MT;
    const int n0 = blockIdx.x * NT;

    const __nv_bfloat16* Ag = (MODE == 0) ? g_emb2 : g_h2[parity];
    const __nv_bfloat16* Bg = (MODE == 0) ? g_wih2 : g_whh2;

    if (MODE == 1) {
        if (tid < 128) {
            ((int*)(smem + SM_CAP))[tid] = cap[(m0 + tid) * TT + t];
            ((int*)(smem + SM_LEN))[tid] = cap_len[m0 + tid];
        }
        if (tid >= 128 && tid < 384)
            ((float*)(smem + SM_BIAS))[tid - 128] = g_bias[n0 + tid - 128];
    }

    // loader geometry (per chunk of 32 k): A = 128x32 bf16, B = 256x32 bf16
    const int a_row = tid >> 2, a_cu = tid & 3;                 // 1 unit of 16B
    const int b_row0 = (tid * 2) >> 2, b_cu0 = (tid * 2) & 3;   // 2 units
    const int b_row1 = (tid * 2 + 1) >> 2, b_cu1 = (tid * 2 + 1) & 3;

    uint32_t stA[3], stB[3];
    #pragma unroll
    for (int s = 0; s < 3; s++) {
        stA[s] = sb + SM_STAGE + s * STAGE_BYTES;
        stB[s] = stA[s] + 10240;
    }

    auto issue_chunk = [&](int c) {
        if (c < NC) {
            const int stage = c % 3;
            const int seg = c / 10, within = (c - seg * 10) * 32;
            const int aoff = ((seg == 1) ? KSEG : 0) + within;
            const int boff = ((seg == 2) ? KSEG : 0) + within;
            cp_async16(stA[stage] + a_row * 80 + a_cu * 16,
                       Ag + (size_t)(m0 + a_row) * KP2 + aoff + a_cu * 8);
            cp_async16(stB[stage] + b_row0 * 80 + b_cu0 * 16,
                       Bg + (size_t)(n0 + b_row0) * KP2 + boff + b_cu0 * 8);
            cp_async16(stB[stage] + b_row1 * 80 + b_cu1 * 16,
                       Bg + (size_t)(n0 + b_row1) * KP2 + boff + b_cu1 * 8);
        }
        cp_commit();
    };

    float acc[4][4][4];
    #pragma unroll
    for (int i = 0; i < 4; i++)
        #pragma unroll
        for (int j = 0; j < 4; j++)
            #pragma unroll
            for (int e = 0; e < 4; e++) acc[i][j][e] = 0.f;

    // ldmatrix per-thread base components
    const uint32_t a_lrow = (uint32_t)(wm * 64 + (lane & 15)) * 80;
    const uint32_t a_kofs = (uint32_t)((lane >> 4) * 8) * 2;
    const uint32_t b_lrow = (uint32_t)(wn * 32 + (lane & 7)) * 80;
    const uint32_t b_kofs = (uint32_t)(((lane >> 3) & 1) * 8) * 2;

    issue_chunk(0);
    issue_chunk(1);

    for (int c = 0; c < NC; c++) {
        cp_wait1();
        __syncthreads();
        const int stage = c % 3;
        const uint32_t sA = stA[stage], sB = stB[stage];
        #pragma unroll
        for (int k16 = 0; k16 < 2; k16++) {
            uint32_t a[4][4], b[4][2];
            #pragma unroll
            for (int i = 0; i < 4; i++)
                ldsm_x4(a[i], sA + a_lrow + i * 16 * 80 + k16 * 32 + a_kofs);
            #pragma unroll
            for (int j = 0; j < 4; j++)
                ldsm_x2(b[j], sB + b_lrow + j * 8 * 80 + k16 * 32 + b_kofs);
            #pragma unroll
            for (int i = 0; i < 4; i++)
                #pragma unroll
                for (int j = 0; j < 4; j++)
                    mma16816(acc[i][j], a[i], b[j]);
        }
        __syncthreads();
        issue_chunk(c + 2);
    }

    // ---------------- epilogue ----------------
    const int lr_base = wm * 64 + (lane >> 2);   // local row (low half)
    const int nl_base = wn * 32 + 2 * (lane & 3);

    if (MODE == 0) {
        #pragma unroll
        for (int i = 0; i < 4; i++) {
            const int r0 = m0 + lr_base + i * 16;
            #pragma unroll
            for (int j = 0; j < 4; j++) {
                const int ng = n0 + nl_base + j * 8;
                *(float2*)(g_xproj + (size_t)r0 * NP + ng) = make_float2(acc[i][j][0], acc[i][j][1]);
                *(float2*)(g_xproj + (size_t)(r0 + 8) * NP + ng) = make_float2(acc[i][j][2], acc[i][j][3]);
            }
        }
    } else {
        const int* s_cap = (const int*)(smem + SM_CAP);
        const int* s_len = (const int*)(smem + SM_LEN);
        const float* s_bias = (const float*)(smem + SM_BIAS);
        __nv_bfloat16* hout = g_h2[parity ^ 1];

        #pragma unroll
        for (int i = 0; i < 4; i++) {
            const int lr0 = lr_base + i * 16;
            const int r0 = m0 + lr0, r1 = r0 + 8;
            const int tok0 = s_cap[lr0], tok1 = s_cap[lr0 + 8];
            const bool last0 = (t == s_len[lr0] - 1);
            const bool last1 = (t == s_len[lr0 + 8] - 1);
            #pragma unroll
            for (int j = 0; j < 4; j++) {
                const int nl = nl_base + j * 8;
                const int ng = n0 + nl;
                const float2 x0 = *(const float2*)(g_xproj + (size_t)tok0 * NP + ng);
                const float2 x1 = *(const float2*)(g_xproj + (size_t)tok1 * NP + ng);
                const float2 bi = *(const float2*)(s_bias + nl);
                float v0 = acc[i][j][0] + x0.x + bi.x;
                float v1 = acc[i][j][1] + x0.y + bi.y;
                float v2 = acc[i][j][2] + x1.x + bi.x;
                float v3 = acc[i][j][3] + x1.y + bi.y;
                // partner exchange: (i,f) <-> (g,o)
                float o0 = __shfl_xor_sync(0xffffffff, v0, 1);
                float o1 = __shfl_xor_sync(0xffffffff, v1, 1);
                float o2 = __shfl_xor_sync(0xffffffff, v2, 1);
                float o3 = __shfl_xor_sync(0xffffffff, v3, 1);
                const bool odd = lane & 1;
                float gi0 = odd ? o0 : v0, gf0 = odd ? o1 : v1;
                float gg0 = odd ? v0 : o0, go0 = odd ? v1 : o1;
                float gi1 = odd ? o2 : v2, gf1 = odd ? o3 : v3;
                float gg1 = odd ? v2 : o2, go1 = odd ? v3 : o3;
                if (!odd) {
                    const int u = ng >> 2;    // hidden unit
                    // row 0
                    {
                        float I = fsig(gi0), F = fsig(gf0), G = ftanh(gg0), O = fsig(go0);
                        float cn = F * g_c[(size_t)r0 * KSEG + u] + I * G;
                        float hn = O * ftanh(cn);
                        g_c[(size_t)r0 * KSEG + u] = cn;
                        __nv_bfloat16 hb = __float2bfloat16_rn(hn);
                        hout[(size_t)r0 * KP2 + u] = hb;
                        hout[(size_t)r0 * KP2 + KSEG + u] =
                            __float2bfloat16_rn(hn - __bfloat162float(hb));
                        if (last0 && u < HH) g_hlast[r0 * HH + u] = hn;
                    }
                    // row 1
                    {
                        float I = fsig(gi1), F = fsig(gf1), G = ftanh(gg1), O = fsig(go1);
                        float cn = F * g_c[(size_t)r1 * KSEG + u] + I * G;
                        float hn = O * ftanh(cn);
                        g_c[(size_t)r1 * KSEG + u] = cn;
                        __nv_bfloat16 hb = __float2bfloat16_rn(hn);
                        hout[(size_t)r1 * KP2 + u] = hb;
                        hout[(size_t)r1 * KP2 + KSEG + u] =
                            __float2bfloat16_rn(hn - __bfloat162float(hb));
                        if (last1 && u < HH) g_hlast[r1 * HH + u] = hn;
                    }
                }
            }
        }
    }
}

// ---------------- classifier ----------------
__global__ void k_cls(const float* __restrict__ cls_b, float* __restrict__ out)
{
    int warp = (blockIdx.x * blockDim.x + threadIdx.x) >> 5;
    int lane = threadIdx.x & 31;
    if (warp >= BB) return;
    float s0 = 0.f, s1 = 0.f;
    for (int k = lane; k < HH; k += 32) {
        float hv = g_hlast[warp * HH + k];
        s0 += hv * g_wn[k];
        s1 += hv * g_wn[HH + k];
    }
    #pragma unroll
    for (int o = 16; o; o >>= 1) {
        s0 += __shfl_xor_sync(0xffffffff, s0, o);
        s1 += __shfl_xor_sync(0xffffffff, s1, o);
    }
    if (lane == 0) {
        out[warp * 2 + 0] = s0 + cls_b[0];
        out[warp * 2 + 1] = s1 + cls_b[1];
    }
}

extern "C" void kernel_launch(void* const* d_in, const int* in_sizes, int n_in,
                              void* d_out, int out_size)
{
    const int*   cap     = (const int*)d_in[0];
    const int*   cap_len = (const int*)d_in[1];
    const float* embed_w = (const float*)d_in[2];
    const float* W_ih    = (const float*)d_in[3];
    const float* W_hh    = (const float*)d_in[4];
    const float* b_ih    = (const float*)d_in[5];
    const float* b_hh    = (const float*)d_in[6];
    const float* cls_v   = (const float*)d_in[7];
    const float* cls_g   = (const float*)d_in[8];
    const float* cls_b   = (const float*)d_in[9];
    float* out = (float*)d_out;

    cudaFuncSetAttribute(k_tgemm<0>, cudaFuncAttributeMaxDynamicSharedMemorySize, SMEM_TOTAL);
    cudaFuncSetAttribute(k_tgemm<1>, cudaFuncAttributeMaxDynamicSharedMemorySize, SMEM_TOTAL);

    k_prep<<<2048, 256>>>(embed_w, W_ih, W_hh, b_ih, b_hh);
    k_prep_cls<<<1, 64>>>(cls_v, cls_g);

    {   // x_proj = emb @ W_ih^T
        dim3 grid(NP / NT, MV / MT);   // (5, 79)
        k_tgemm<0><<<grid, 512, SMEM_TOTAL>>>(0, 0, nullptr, nullptr);
    }
    {   // 32 fused recurrent steps
        dim3 grid(NP / NT, BB / MT);   // (5, 32) = 160 CTAs
        for (int t = 0; t < TT; t++)
            k_tgemm<1><<<grid, 512, SMEM_TOTAL>>>(t, t & 1, cap, cap_len);
    }
    k_cls<<<512, 256>>>(cls_b, out);
}

// round 7
// speedup vs baseline: 1.9649x; 1.3226x over previous
#include <cuda_runtime.h>
#include <cuda_bf16.h>
#include <math.h>
#include <stdint.h>

// ---------------- problem constants ----------------
#define BB    4096
#define TT    32
#define VOCAB 10000
#define EE    300
#define HH    300
#define KSEG  320      // padded K per segment
#define KP2   640      // hi|lo storage columns
#define NP    1280     // 4H padded
#define MV    10112    // vocab padded to 128
#define NC    30       // K chunks of 32 (3 segments x 10)
#define MT    128
#define NT    128
#define NSTAGE 4

// smem (dynamic) layout, bytes
#define SM_CAP   0          // 128 int
#define SM_LEN   512        // 128 int
#define SM_BIAS  1024       // 128 float
#define SM_STAGE 2048       // 4 stages x (A 10240 + B 10240)
#define STAGE_BYTES 20480
#define SMEM_TOTAL (SM_STAGE + NSTAGE * STAGE_BYTES)   // 83968

// ---------------- device scratch ----------------
__device__ __nv_bfloat16 g_emb2[(size_t)MV * KP2];
__device__ __nv_bfloat16 g_wih2[(size_t)NP * KP2];
__device__ __nv_bfloat16 g_whh2[(size_t)NP * KP2];
__device__ float         g_bias[NP];
__device__ float         g_xproj[(size_t)MV * NP];
__device__ __nv_bfloat16 g_h2[2][(size_t)BB * KP2];
__device__ float         g_c[(size_t)BB * KSEG];
__device__ float         g_hlast[BB * HH];
__device__ float         g_wn[2 * HH];

// ---------------- PTX helpers (plain sm_80+ instructions only) ----------------
__device__ __forceinline__ uint32_t smem_u32(const void* p) {
    uint32_t a;
    asm("{ .reg .u64 t; cvta.to.shared.u64 t, %1; cvt.u32.u64 %0, t; }" : "=r"(a) : "l"(p));
    return a;
}
__device__ __forceinline__ void cp_async16(uint32_t s, const void* g) {
    asm volatile("cp.async.cg.shared.global [%0], [%1], 16;" :: "r"(s), "l"(g) : "memory");
}
__device__ __forceinline__ void cp_commit() {
    asm volatile("cp.async.commit_group;" ::: "memory");
}
__device__ __forceinline__ void cp_wait2() {
    asm volatile("cp.async.wait_group 2;" ::: "memory");
}
__device__ __forceinline__ void ldsm_x4(uint32_t* r, uint32_t addr) {
    asm volatile("ldmatrix.sync.aligned.m8n8.x4.shared.b16 {%0,%1,%2,%3}, [%4];"
                 : "=r"(r[0]), "=r"(r[1]), "=r"(r[2]), "=r"(r[3]) : "r"(addr));
}
__device__ __forceinline__ void ldsm_x2(uint32_t* r, uint32_t addr) {
    asm volatile("ldmatrix.sync.aligned.m8n8.x2.shared.b16 {%0,%1}, [%2];"
                 : "=r"(r[0]), "=r"(r[1]) : "r"(addr));
}
__device__ __forceinline__ void mma16816(float* c, const uint32_t* a, const uint32_t* b) {
    asm volatile(
        "mma.sync.aligned.m16n8k16.row.col.f32.bf16.bf16.f32 "
        "{%0,%1,%2,%3}, {%4,%5,%6,%7}, {%8,%9}, {%0,%1,%2,%3};"
        : "+f"(c[0]), "+f"(c[1]), "+f"(c[2]), "+f"(c[3])
        : "r"(a[0]), "r"(a[1]), "r"(a[2]), "r"(a[3]), "r"(b[0]), "r"(b[1]));
}
__device__ __forceinline__ float fsig(float x)  { return 1.f / (1.f + __expf(-x)); }
__device__ __forceinline__ float ftanh(float x) { return 1.f - 2.f / (1.f + __expf(2.f * x)); }

// ---------------- prep: fp32 -> bf16 hi|lo split, gate interleave, zero state ----------------
__global__ void k_prep(const float* __restrict__ embed_w,
                       const float* __restrict__ W_ih,
                       const float* __restrict__ W_hh,
                       const float* __restrict__ b_ih,
                       const float* __restrict__ b_hh)
{
    const int stride = gridDim.x * blockDim.x;
    const int i0 = blockIdx.x * blockDim.x + threadIdx.x;

    for (size_t idx = i0; idx < (size_t)MV * KP2; idx += stride) {
        int r = idx / KP2, k2 = idx - (size_t)r * KP2;
        int k = (k2 >= KSEG) ? k2 - KSEG : k2;
        float v = (r < VOCAB && k < EE) ? embed_w[r * EE + k] : 0.f;
        __nv_bfloat16 hi = __float2bfloat16_rn(v);
        g_emb2[idx] = (k2 >= KSEG) ? __float2bfloat16_rn(v - __bfloat162float(hi)) : hi;
    }
    for (size_t idx = i0; idx < (size_t)NP * KP2; idx += stride) {
        int n = idx / KP2, k2 = idx - (size_t)n * KP2;
        int k = (k2 >= KSEG) ? k2 - KSEG : k2;
        int gs = n & 3, u = n >> 2;
        float vi = 0.f, vh = 0.f;
        if (u < HH && k < EE) {
            int s = (gs * HH + u) * EE + k;
            vi = W_ih[s];
            vh = W_hh[s];
        }
        __nv_bfloat16 hi_i = __float2bfloat16_rn(vi);
        __nv_bfloat16 hi_h = __float2bfloat16_rn(vh);
        if (k2 >= KSEG) {
            g_wih2[idx] = __float2bfloat16_rn(vi - __bfloat162float(hi_i));
            g_whh2[idx] = __float2bfloat16_rn(vh - __bfloat162float(hi_h));
        } else {
            g_wih2[idx] = hi_i;
            g_whh2[idx] = hi_h;
        }
    }
    for (int n = i0; n < NP; n += stride) {
        int gs = n & 3, u = n >> 2;
        g_bias[n] = (u < HH) ? (b_ih[gs * HH + u] + b_hh[gs * HH + u]) : 0.f;
    }
    for (size_t idx = i0; idx < (size_t)BB * KP2; idx += stride) {
        g_h2[0][idx] = __float2bfloat16_rn(0.f);
        g_h2[1][idx] = __float2bfloat16_rn(0.f);
    }
    for (size_t idx = i0; idx < (size_t)BB * KSEG; idx += stride)
        g_c[idx] = 0.f;
}

__global__ void k_prep_cls(const float* __restrict__ cls_v,
                           const float* __restrict__ cls_g)
{
    int w = threadIdx.x >> 5;
    int lane = threadIdx.x & 31;
    if (w >= 2) return;
    float s = 0.f;
    for (int k = lane; k < HH; k += 32) {
        float v = cls_v[w * HH + k];
        s += v * v;
    }
    #pragma unroll
    for (int o = 16; o; o >>= 1) s += __shfl_xor_sync(0xffffffff, s, o);
    float scale = cls_g[w] / sqrtf(s);
    for (int k = lane; k < HH; k += 32)
        g_wn[w * HH + k] = cls_v[w * HH + k] * scale;
}

// ---------------- HMMA GEMM: C[128,128] = A[128,960] x B[128,960]^T ----------------
// Extended K: A chunks [hi|lo|hi], B chunks [hi|hi|lo]
// MODE 0: A=g_emb2, B=g_wih2 -> store g_xproj
// MODE 1: A=g_h2[parity], B=g_whh2 -> fused LSTM epilogue
template <int MODE>
__global__ void __launch_bounds__(256, 2) k_tgemm(int t, int parity,
                                                  const int* __restrict__ cap,
                                                  const int* __restrict__ cap_len)
{
    extern __shared__ char smem[];
    const uint32_t sb = smem_u32(smem);
    const int tid = threadIdx.x;
    const int wid = tid >> 5;
    const int lane = tid & 31;
    const int wm = wid >> 2;         // 0..1 : 64-row slice
    const int wn = wid & 3;          // 0..3 : 32-col slice
    const int m0 = blockIdx.y * MT;
    const int n0 = blockIdx.x * NT;

    const __nv_bfloat16* Ag = (MODE == 0) ? g_emb2 : g_h2[parity];
    const __nv_bfloat16* Bg = (MODE == 0) ? g_wih2 : g_whh2;

    if (MODE == 1) {
        if (tid < 128) {
            ((int*)(smem + SM_CAP))[tid] = cap[(m0 + tid) * TT + t];
            ((int*)(smem + SM_LEN))[tid] = cap_len[m0 + tid];
        } else {
            ((float*)(smem + SM_BIAS))[tid - 128] = g_bias[n0 + tid - 128];
        }
    }

    // loader geometry: per chunk A = 128x32 bf16 (128 rows x 4 x 16B), B same.
    // 256 threads x 2 units each for A, 2 for B.
    const int a_row = tid >> 1;
    const int a_cu  = (tid & 1) * 2;

    uint32_t stA[NSTAGE], stB[NSTAGE];
    #pragma unroll
    for (int s = 0; s < NSTAGE; s++) {
        stA[s] = sb + SM_STAGE + s * STAGE_BYTES;
        stB[s] = stA[s] + 10240;
    }

    auto issue_chunk = [&](int c) {
        if (c < NC) {
            const int stage = c & 3;
            const int seg = c / 10, within = (c - seg * 10) * 32;
            const int aoff = ((seg == 1) ? KSEG : 0) + within;
            const int boff = ((seg == 2) ? KSEG : 0) + within;
            const __nv_bfloat16* ap = Ag + (size_t)(m0 + a_row) * KP2 + aoff + a_cu * 8;
            const __nv_bfloat16* bp = Bg + (size_t)(n0 + a_row) * KP2 + boff + a_cu * 8;
            const uint32_t sa = stA[stage] + a_row * 80 + a_cu * 16;
            const uint32_t sbm = stB[stage] + a_row * 80 + a_cu * 16;
            cp_async16(sa, ap);
            cp_async16(sa + 16, ap + 8);
            cp_async16(sbm, bp);
            cp_async16(sbm + 16, bp + 8);
        }
        cp_commit();
    };

    float acc[4][4][4];
    #pragma unroll
    for (int i = 0; i < 4; i++)
        #pragma unroll
        for (int j = 0; j < 4; j++)
            #pragma unroll
            for (int e = 0; e < 4; e++) acc[i][j][e] = 0.f;

    const uint32_t a_lrow = (uint32_t)(wm * 64 + (lane & 15)) * 80;
    const uint32_t a_kofs = (uint32_t)((lane >> 4) * 8) * 2;
    const uint32_t b_lrow = (uint32_t)(wn * 32 + (lane & 7)) * 80;
    const uint32_t b_kofs = (uint32_t)(((lane >> 3) & 1) * 8) * 2;

    issue_chunk(0);
    issue_chunk(1);
    issue_chunk(2);

    for (int c = 0; c < NC; c++) {
        cp_wait2();
        __syncthreads();
        issue_chunk(c + 3);                 // into stage freed by previous iteration
        const int stage = c & 3;
        const uint32_t sA = stA[stage], sB = stB[stage];
        #pragma unroll
        for (int k16 = 0; k16 < 2; k16++) {
            uint32_t a[4][4], b[4][2];
            #pragma unroll
            for (int i = 0; i < 4; i++)
                ldsm_x4(a[i], sA + a_lrow + i * 16 * 80 + k16 * 32 + a_kofs);
            #pragma unroll
            for (int j = 0; j < 4; j++)
                ldsm_x2(b[j], sB + b_lrow + j * 8 * 80 + k16 * 32 + b_kofs);
            #pragma unroll
            for (int i = 0; i < 4; i++)
                #pragma unroll
                for (int j = 0; j < 4; j++)
                    mma16816(acc[i][j], a[i], b[j]);
        }
    }

    // ---------------- epilogue ----------------
    const int lr_base = wm * 64 + (lane >> 2);
    const int nl_base = wn * 32 + 2 * (lane & 3);
    const bool odd = lane & 1;

    if (MODE == 0) {
        #pragma unroll
        for (int i = 0; i < 4; i++) {
            const int r0 = m0 + lr_base + i * 16;
            #pragma unroll
            for (int j = 0; j < 4; j++) {
                const int ng = n0 + nl_base + j * 8;
                *(float2*)(g_xproj + (size_t)r0 * NP + ng) = make_float2(acc[i][j][0], acc[i][j][1]);
                *(float2*)(g_xproj + (size_t)(r0 + 8) * NP + ng) = make_float2(acc[i][j][2], acc[i][j][3]);
            }
        }
    } else {
        const int* s_cap = (const int*)(smem + SM_CAP);
        const int* s_len = (const int*)(smem + SM_LEN);
        const float* s_bias = (const float*)(smem + SM_BIAS);
        __nv_bfloat16* hout = g_h2[parity ^ 1];

        #pragma unroll
        for (int i = 0; i < 4; i++) {
            const int lr0 = lr_base + i * 16;
            const int r0 = m0 + lr0, r1 = r0 + 8;
            const int tok0 = s_cap[lr0], tok1 = s_cap[lr0 + 8];
            // this lane finishes one of the two rows
            const int  rme   = odd ? r1 : r0;
            const bool lastme = odd ? (t == s_len[lr0 + 8] - 1) : (t == s_len[lr0] - 1);
            #pragma unroll
            for (int j = 0; j < 4; j++) {
                const int nl = nl_base + j * 8;
                const int ng = n0 + nl;
                const float2 x0 = *(const float2*)(g_xproj + (size_t)tok0 * NP + ng);
                const float2 x1 = *(const float2*)(g_xproj + (size_t)tok1 * NP + ng);
                const float2 bi = *(const float2*)(s_bias + nl);
                float v0 = acc[i][j][0] + x0.x + bi.x;
                float v1 = acc[i][j][1] + x0.y + bi.y;
                float v2 = acc[i][j][2] + x1.x + bi.x;
                float v3 = acc[i][j][3] + x1.y + bi.y;
                // partner exchange: even lane owns (i,f), odd owns (g,o)
                float o0 = __shfl_xor_sync(0xffffffff, v0, 1);
                float o1 = __shfl_xor_sync(0xffffffff, v1, 1);
                float o2 = __shfl_xor_sync(0xffffffff, v2, 1);
                float o3 = __shfl_xor_sync(0xffffffff, v3, 1);
                // even lane computes row0, odd lane computes row1
                float gi, gf, gg, go;
                if (!odd) { gi = v0; gf = v1; gg = o0; go = o1; }   // row0
                else      { gi = o2; gf = o3; gg = v2; go = v3; }   // row1
                const int u = (ng - (odd ? 2 : 0)) >> 2;            // hidden unit
                float I = fsig(gi), F = fsig(gf), G = ftanh(gg), O = fsig(go);
                float cn = F * g_c[(size_t)rme * KSEG + u] + I * G;
                float hn = O * ftanh(cn);
                g_c[(size_t)rme * KSEG + u] = cn;
                __nv_bfloat16 hb = __float2bfloat16_rn(hn);
                hout[(size_t)rme * KP2 + u] = hb;
                hout[(size_t)rme * KP2 + KSEG + u] =
                    __float2bfloat16_rn(hn - __bfloat162float(hb));
                if (lastme && u < HH) g_hlast[rme * HH + u] = hn;
            }
        }
    }
}

// ---------------- classifier ----------------
__global__ void k_cls(const float* __restrict__ cls_b, float* __restrict__ out)
{
    int warp = (blockIdx.x * blockDim.x + threadIdx.x) >> 5;
    int lane = threadIdx.x & 31;
    if (warp >= BB) return;
    float s0 = 0.f, s1 = 0.f;
    for (int k = lane; k < HH; k += 32) {
        float hv = g_hlast[warp * HH + k];
        s0 += hv * g_wn[k];
        s1 += hv * g_wn[HH + k];
    }
    #pragma unroll
    for (int o = 16; o; o >>= 1) {
        s0 += __shfl_xor_sync(0xffffffff, s0, o);
        s1 += __shfl_xor_sync(0xffffffff, s1, o);
    }
    if (lane == 0) {
        out[warp * 2 + 0] = s0 + cls_b[0];
        out[warp * 2 + 1] = s1 + cls_b[1];
    }
}

extern "C" void kernel_launch(void* const* d_in, const int* in_sizes, int n_in,
                              void* d_out, int out_size)
{
    const int*   cap     = (const int*)d_in[0];
    const int*   cap_len = (const int*)d_in[1];
    const float* embed_w = (const float*)d_in[2];
    const float* W_ih    = (const float*)d_in[3];
    const float* W_hh    = (const float*)d_in[4];
    const float* b_ih    = (const float*)d_in[5];
    const float* b_hh    = (const float*)d_in[6];
    const float* cls_v   = (const float*)d_in[7];
    const float* cls_g   = (const float*)d_in[8];
    const float* cls_b   = (const float*)d_in[9];
    float* out = (float*)d_out;

    cudaFuncSetAttribute(k_tgemm<0>, cudaFuncAttributeMaxDynamicSharedMemorySize, SMEM_TOTAL);
    cudaFuncSetAttribute(k_tgemm<1>, cudaFuncAttributeMaxDynamicSharedMemorySize, SMEM_TOTAL);

    k_prep<<<2048, 256>>>(embed_w, W_ih, W_hh, b_ih, b_hh);
    k_prep_cls<<<1, 64>>>(cls_v, cls_g);

    {   // x_proj = emb @ W_ih^T
        dim3 grid(NP / NT, MV / MT);   // (10, 79)
        k_tgemm<0><<<grid, 256, SMEM_TOTAL>>>(0, 0, nullptr, nullptr);
    }
    {   // 32 fused recurrent steps
        dim3 grid(NP / NT, BB / MT);   // (10, 32) = 320 CTAs, 2 per SM
        for (int t = 0; t < TT; t++)
            k_tgemm<1><<<grid, 256, SMEM_TOTAL>>>(t, t & 1, cap, cap_len);
    }
    k_cls<<<512, 256>>>(cls_b, out);
}